// round 4
// baseline (speedup 1.0000x reference)
#include <cuda_runtime.h>
#include <cuda_bf16.h>
#include <cstdint>
#include <math.h>

#define N_ROWS 65536
#define DIM    512
#define KCODES 1024

#define QUANT_OFF 1
#define PERP_OFF  (1 + N_ROWS * DIM)
#define ENC_OFF   (2 + (size_t)N_ROWS * DIM)

// pass-1 GEMM tiling
#define M_TILE 128
#define N_TILE 256
#define ASTRIDE 1040            // bytes per A smem row (520 bf16, conflict-free)
#define BSTRIDE 144             // bytes per B smem row (72 bf16)
#define SMA     0               // A: 128 x 1040B = 133120
#define SMB     133120          // B: 2 bufs x 256 x 144B
#define SMB_BUF 36864
#define SMWN    206848          // 256 f32
#define SMXN    207872          // 128 f32
#define SMMIN   208384          // 128 u64
#define SMCNT   209408          // 128 u32
#define SMCAND  209920          // 128 x 32 u16
#define SMTOT   218112
#define MARGIN  0.03125f

// ---- scratch ----
__device__ __align__(16) __nv_bfloat16 g_xbf[(size_t)N_ROWS * DIM];
__device__ __align__(16) __nv_bfloat16 g_wbf[KCODES * DIM];
__device__ float  g_wnorm[KCODES];
__device__ float  g_xnorm[N_ROWS];
__device__ int    g_idx[N_ROWS];
__device__ int    g_counts[KCODES];
__device__ unsigned short g_cand[(size_t)N_ROWS * 32];
__device__ int    g_ccount[N_ROWS];
__device__ double g_sse;

// ---- asm helpers (baseline PTX only: sm_80-era ops) ----
static __device__ __forceinline__ uint32_t smem_u32(const void* p) {
    uint32_t a;
    asm("{ .reg .u64 t; cvta.to.shared.u64 t, %1; cvt.u32.u64 %0, t; }" : "=r"(a) : "l"(p));
    return a;
}
static __device__ __forceinline__ uint64_t cvta_g(const void* p) {
    uint64_t a; asm("cvta.to.global.u64 %0, %1;" : "=l"(a) : "l"(p)); return a;
}
static __device__ __forceinline__ void cp16(uint32_t s, uint64_t g) {
    asm volatile("cp.async.cg.shared.global [%0], [%1], 16;" :: "r"(s), "l"(g));
}
#define CP_COMMIT() asm volatile("cp.async.commit_group;")
#define CP_WAIT0()  asm volatile("cp.async.wait_group 0;")

static __device__ __forceinline__ void ldsm4(uint32_t* r, uint32_t a) {
    asm volatile("ldmatrix.sync.aligned.m8n8.x4.shared.b16 {%0,%1,%2,%3}, [%4];"
                 : "=r"(r[0]), "=r"(r[1]), "=r"(r[2]), "=r"(r[3]) : "r"(a));
}
static __device__ __forceinline__ void mma_bf16(float* c, const uint32_t* a,
                                                const uint32_t* b) {
    asm volatile(
        "mma.sync.aligned.m16n8k16.row.col.f32.bf16.bf16.f32 "
        "{%0,%1,%2,%3}, {%4,%5,%6,%7}, {%8,%9}, {%0,%1,%2,%3};"
        : "+f"(c[0]), "+f"(c[1]), "+f"(c[2]), "+f"(c[3])
        : "r"(a[0]), "r"(a[1]), "r"(a[2]), "r"(a[3]), "r"(b[0]), "r"(b[1]));
}

// ============================================================
// prep W: wnorm + bf16 copy + zero counts/sse
// ============================================================
__global__ void vq_wprep(const float* __restrict__ W) {
    int w = threadIdx.x >> 5, lane = threadIdx.x & 31;
    int code = blockIdx.x * 8 + w;
    const float* row = W + (size_t)code * DIM;
    float s = 0.f;
#pragma unroll
    for (int t = 0; t < 16; t++) {
        float v = row[lane + t * 32];
        s += v * v;
        g_wbf[(size_t)code * DIM + lane + t * 32] = __float2bfloat16_rn(v);
    }
#pragma unroll
    for (int o = 16; o > 0; o >>= 1) s += __shfl_down_sync(0xffffffffu, s, o);
    if (lane == 0) g_wnorm[code] = s;
    if (blockIdx.x == 0) {
        for (int i = threadIdx.x; i < KCODES; i += blockDim.x) g_counts[i] = 0;
        if (threadIdx.x == 0) g_sse = 0.0;
    }
}

// prep X: xnorm + bf16 copy
__global__ void vq_xprep(const float* __restrict__ X) {
    int w = threadIdx.x >> 5, lane = threadIdx.x & 31;
    int r = blockIdx.x * 8 + w;
    const float* row = X + (size_t)r * DIM;
    float s = 0.f;
#pragma unroll
    for (int t = 0; t < 16; t++) {
        float v = row[lane + t * 32];
        s += v * v;
        g_xbf[(size_t)r * DIM + lane + t * 32] = __float2bfloat16_rn(v);
    }
#pragma unroll
    for (int o = 16; o > 0; o >>= 1) s += __shfl_down_sync(0xffffffffu, s, o);
    if (lane == 0) g_xnorm[r] = s;
}

// ============================================================
// pass 1: bf16 mma.sync GEMM + candidate collection
// CTA: 128 rows x 1024 codes (4 n-chunks of 256); 8 warps, warp tile 64x64
// ============================================================
__global__ void __launch_bounds__(256, 1)
vq_pass1(void) {
    extern __shared__ __align__(1024) char smem[];
    const uint32_t sb = smem_u32(smem);
    const int tid = threadIdx.x;
    const int lane = tid & 31, wid = tid >> 5;
    const int warp_m = (wid >> 2) * 64, warp_n = (wid & 3) * 64;
    const int r0 = blockIdx.x * M_TILE;

    float* sWn = (float*)(smem + SMWN);
    float* sXn = (float*)(smem + SMXN);
    unsigned long long* sMin = (unsigned long long*)(smem + SMMIN);
    int* sCnt = (int*)(smem + SMCNT);
    unsigned short* sCand = (unsigned short*)(smem + SMCAND);

    // stage A once (bf16, k-resident), issue async
    {
        uint64_t xsrc = cvta_g(g_xbf) + (size_t)r0 * (DIM * 2);
#pragma unroll
        for (int i = 0; i < 32; i++) {
            int f = tid + i * 256;              // 0..8191 16B chunks
            int row = f >> 6, j = f & 63;
            cp16(sb + SMA + row * ASTRIDE + j * 16, xsrc + row * 1024 + j * 16);
        }
    }
    // stage B chunk (nc=0, kc=0) into buf0
    {
        uint64_t wsrc = cvta_g(g_wbf);
#pragma unroll
        for (int i = 0; i < 8; i++) {
            int f = tid + i * 256;              // 0..2047
            int n = f >> 3, j = f & 7;
            cp16(sb + SMB + n * BSTRIDE + j * 16, wsrc + (size_t)n * 1024 + j * 16);
        }
    }
    CP_COMMIT();

    if (tid < M_TILE) {
        sXn[tid] = g_xnorm[r0 + tid];
        sMin[tid] = 0xFFFFFFFFFFFFFFFFull;
        sCnt[tid] = 0;
    }

    // per-lane ldmatrix base addresses
    const uint32_t aLane = sb + SMA
        + (warp_m + (lane & 7) + ((lane >> 3) & 1) * 8) * ASTRIDE
        + (lane >> 4) * 16;
    const uint32_t bLane0 = sb + SMB
        + (warp_n + (lane & 7) + ((lane >> 4) & 1) * 8) * BSTRIDE
        + ((lane >> 3) & 1) * 16;

    for (int nc = 0; nc < 4; nc++) {
        const int c0 = nc * N_TILE;
        CP_WAIT0();
        __syncthreads();                 // staged data visible; prev epilogue done
        sWn[tid] = g_wnorm[c0 + tid];    // 256 threads -> 256 entries

        float acc[4][8][4];
#pragma unroll
        for (int mf = 0; mf < 4; mf++)
#pragma unroll
            for (int nf = 0; nf < 8; nf++)
#pragma unroll
                for (int e = 0; e < 4; e++) acc[mf][nf][e] = 0.f;

        for (int kc = 0; kc < 8; kc++) {
            const int buf = kc & 1;
            if (kc < 7) {                // prefetch next k-chunk into other buf
                uint64_t wsrc = cvta_g(g_wbf) + (size_t)c0 * 1024 + (kc + 1) * 128;
#pragma unroll
                for (int i = 0; i < 8; i++) {
                    int f = tid + i * 256;
                    int n = f >> 3, j = f & 7;
                    cp16(sb + SMB + (buf ^ 1) * SMB_BUF + n * BSTRIDE + j * 16,
                         wsrc + (size_t)n * 1024 + j * 16);
                }
                CP_COMMIT();
            }
#pragma unroll
            for (int s = 0; s < 4; s++) {
                uint32_t a[4][4], b[4][4];
#pragma unroll
                for (int mf = 0; mf < 4; mf++)
                    ldsm4(a[mf], aLane + mf * (16 * ASTRIDE) + (kc * 64 + s * 16) * 2);
#pragma unroll
                for (int nb = 0; nb < 4; nb++)
                    ldsm4(b[nb], bLane0 + buf * SMB_BUF + nb * (16 * BSTRIDE) + s * 32);
#pragma unroll
                for (int mf = 0; mf < 4; mf++)
#pragma unroll
                    for (int nf = 0; nf < 8; nf++)
                        mma_bf16(acc[mf][nf], a[mf], &b[nf >> 1][(nf & 1) * 2]);
            }
            if (kc < 7) {
                CP_WAIT0();
                __syncthreads();
            }
        }

        // prefetch next nc's first B chunk (overlaps epilogue)
        if (nc < 3) {
            uint64_t wsrc = cvta_g(g_wbf) + (size_t)(c0 + N_TILE) * 1024;
#pragma unroll
            for (int i = 0; i < 8; i++) {
                int f = tid + i * 256;
                int n = f >> 3, j = f & 7;
                cp16(sb + SMB + n * BSTRIDE + j * 16, wsrc + (size_t)n * 1024 + j * 16);
            }
            CP_COMMIT();
        }

        // ---- epilogue: per-row min, then candidate collection ----
#pragma unroll
        for (int mf = 0; mf < 4; mf++)
#pragma unroll
            for (int h = 0; h < 2; h++) {
                int rl = warp_m + mf * 16 + (lane >> 2) + h * 8;
                float xn = sXn[rl];
                unsigned long long pk = 0xFFFFFFFFFFFFFFFFull;
#pragma unroll
                for (int nf = 0; nf < 8; nf++)
#pragma unroll
                    for (int e = 0; e < 2; e++) {
                        int cl = warp_n + nf * 8 + (lane & 3) * 2 + e;
                        float d = (xn + sWn[cl]) - 2.0f * acc[mf][nf][h * 2 + e];
                        unsigned long long p =
                            ((unsigned long long)__float_as_uint(d) << 32)
                            | (unsigned)(c0 + cl);
                        if (p < pk) pk = p;
                    }
                atomicMin(&sMin[rl], pk);
            }
        __syncthreads();
#pragma unroll
        for (int mf = 0; mf < 4; mf++)
#pragma unroll
            for (int h = 0; h < 2; h++) {
                int rl = warp_m + mf * 16 + (lane >> 2) + h * 8;
                float xn = sXn[rl];
                float thr = __uint_as_float((unsigned)(sMin[rl] >> 32)) + MARGIN;
#pragma unroll
                for (int nf = 0; nf < 8; nf++)
#pragma unroll
                    for (int e = 0; e < 2; e++) {
                        int cl = warp_n + nf * 8 + (lane & 3) * 2 + e;
                        float d = (xn + sWn[cl]) - 2.0f * acc[mf][nf][h * 2 + e];
                        if (d <= thr) {
                            int pos = atomicAdd(&sCnt[rl], 1);
                            if (pos < 32)
                                sCand[rl * 32 + pos] = (unsigned short)(c0 + cl);
                        }
                    }
            }
    }

    __syncthreads();
    if (tid < M_TILE) {
        int r = r0 + tid;
        int cnt = sCnt[tid];
        g_ccount[r] = cnt;
        int m = cnt < 32 ? cnt : 32;
        for (int i = 0; i < m; i++) g_cand[(size_t)r * 32 + i] = sCand[tid * 32 + i];
    }
}

// ============================================================
// pass 2: exact fp32 verify of candidates; first-index tie-break
// ============================================================
__global__ void __launch_bounds__(256)
vq_pass2(const float* __restrict__ X, const float* __restrict__ W) {
    const int w = threadIdx.x >> 5, lane = threadIdx.x & 31;
    const int r = blockIdx.x * 8 + w;
    const float* xr = X + (size_t)r * DIM;
    float xv[16];
#pragma unroll
    for (int i = 0; i < 16; i++) xv[i] = xr[lane + 32 * i];
    const float xn = g_xnorm[r];
    const int cnt = g_ccount[r];
    unsigned long long best = 0xFFFFFFFFFFFFFFFFull;

    if (cnt <= 32) {
        for (int c = 0; c < cnt; c++) {
            int idx = g_cand[(size_t)r * 32 + c];
            const float* wr = W + (size_t)idx * DIM;
            float s = 0.f;
#pragma unroll
            for (int i = 0; i < 16; i++) s += xv[i] * wr[lane + 32 * i];
#pragma unroll
            for (int o = 16; o > 0; o >>= 1) s += __shfl_xor_sync(0xffffffffu, s, o);
            float d = (xn + g_wnorm[idx]) - 2.0f * s;
            unsigned long long p =
                ((unsigned long long)__float_as_uint(d) << 32) | (unsigned)idx;
            if (p < best) best = p;
        }
    } else {                              // overflow: exact scan of all codes
        for (int idx = 0; idx < KCODES; idx++) {
            const float* wr = W + (size_t)idx * DIM;
            float s = 0.f;
#pragma unroll
            for (int i = 0; i < 16; i++) s += xv[i] * wr[lane + 32 * i];
#pragma unroll
            for (int o = 16; o > 0; o >>= 1) s += __shfl_xor_sync(0xffffffffu, s, o);
            float d = (xn + g_wnorm[idx]) - 2.0f * s;
            unsigned long long p =
                ((unsigned long long)__float_as_uint(d) << 32) | (unsigned)idx;
            if (p < best) best = p;
        }
    }
    if (lane == 0) {
        int idx = (int)(best & 0xFFFFFFFFu);
        g_idx[r] = idx;
        atomicAdd(&g_counts[idx], 1);
    }
}

// ============================================================
// output: quantized_st + encodings + SSE
// outq is out+1 (only 4B-aligned) -> scalar stores.
// oute is 8B-aligned -> float2 stores.
// ============================================================
__global__ void __launch_bounds__(256)
vq_output_kernel(const float* __restrict__ X, const float* __restrict__ W,
                 float* __restrict__ outq, float* __restrict__ oute) {
    const int tid = threadIdx.x;
    const int r0  = blockIdx.x * 64;
    const int sub = tid >> 7, c4 = tid & 127;
    double lsum = 0.0;
#pragma unroll 4
    for (int i = 0; i < 32; i++) {
        int r = r0 + i * 2 + sub;
        int idx = g_idx[r];
        float4 xv = ((const float4*)(X + (size_t)r * DIM))[c4];
        float4 qv = ((const float4*)(W + (size_t)idx * DIM))[c4];
        float dx = qv.x - xv.x, dy = qv.y - xv.y, dz = qv.z - xv.z, dw = qv.w - xv.w;
        float* op = outq + (size_t)r * DIM + c4 * 4;
        op[0] = xv.x + dx; op[1] = xv.y + dy;       // scalar STG.32 (4B-aligned dst)
        op[2] = xv.z + dz; op[3] = xv.w + dw;
        lsum += (double)dx * dx + (double)dy * dy + (double)dz * dz + (double)dw * dw;
    }
    float2 z2 = make_float2(0.f, 0.f);
    for (int f = tid; f < 64 * (KCODES / 2); f += 256) {   // float2 zero-fill
        int row = f >> 9, q = f & 511;
        ((float2*)(oute + (size_t)(r0 + row) * KCODES))[q] = z2;
    }
    __syncthreads();
    if (tid < 64) {
        int r = r0 + tid;
        oute[(size_t)r * KCODES + g_idx[r]] = 1.0f;
    }
#pragma unroll
    for (int o = 16; o > 0; o >>= 1) lsum += __shfl_down_sync(0xffffffffu, lsum, o);
    __shared__ double sd[8];
    if ((tid & 31) == 0) sd[tid >> 5] = lsum;
    __syncthreads();
    if (tid == 0) {
        double t = 0.0;
        for (int v = 0; v < 8; v++) t += sd[v];
        atomicAdd(&g_sse, t);
    }
}

// ============================================================
__global__ void vq_finalize_kernel(float* __restrict__ out) {
    __shared__ float red[32];
    int tid = threadIdx.x;
    float p = (float)g_counts[tid] / 65536.0f;
    float t = p * logf(p + 1e-10f);
#pragma unroll
    for (int o = 16; o > 0; o >>= 1) t += __shfl_down_sync(0xffffffffu, t, o);
    if ((tid & 31) == 0) red[tid >> 5] = t;
    __syncthreads();
    if (tid < 32) {
        float v = red[tid];
#pragma unroll
        for (int o = 16; o > 0; o >>= 1) v += __shfl_down_sync(0xffffffffu, v, o);
        if (tid == 0) {
            out[PERP_OFF] = expf(-v);
            float m = (float)(g_sse / 33554432.0);
            out[0] = m + 0.25f * m;
        }
    }
}

// ============================================================
extern "C" void kernel_launch(void* const* d_in, const int* in_sizes, int n_in,
                              void* d_out, int out_size) {
    const float* X = (const float*)d_in[0];
    const float* W = (const float*)d_in[1];
    if (n_in >= 2 && in_sizes[0] == KCODES * DIM && in_sizes[1] == N_ROWS * DIM) {
        const float* t = X; X = W; W = t;
    }
    float* out  = (float*)d_out;
    float* outq = out + QUANT_OFF;
    float* oute = out + ENC_OFF;

    cudaFuncSetAttribute(vq_pass1,
                         cudaFuncAttributeMaxDynamicSharedMemorySize, SMTOT);

    vq_wprep<<<128, 256>>>(W);
    vq_xprep<<<N_ROWS / 8, 256>>>(X);
    vq_pass1<<<N_ROWS / M_TILE, 256, SMTOT>>>();
    vq_pass2<<<N_ROWS / 8, 256>>>(X, W);
    vq_output_kernel<<<1024, 256>>>(X, W, outq, oute);
    vq_finalize_kernel<<<1, 1024>>>(out);
}